// round 1
// baseline (speedup 1.0000x reference)
#include <cuda_runtime.h>
#include <cuda_bf16.h>
#include <cstdint>

// Problem constants (fixed by the dataset)
#define MAX_N 100000
#define MAX_E 1600000

// Scratch (device globals: no allocation allowed)
__device__ float g_h[(size_t)MAX_N * 64];   // post-GEMM features
__device__ float g_y[(size_t)MAX_N * 64];   // aggregated features
__device__ int   g_deg[MAX_N];              // in-degree (excl self loop)
__device__ float g_dis[MAX_N];              // rsqrt(deg+1)

// ---------------------------------------------------------------------------
// degree / normalization
// ---------------------------------------------------------------------------
__global__ void zero_deg_kernel(int* __restrict__ deg, int n) {
    int i = blockIdx.x * blockDim.x + threadIdx.x;
    if (i < n) deg[i] = 0;
}

__global__ void degree_kernel(const int* __restrict__ dst, int E, int* __restrict__ deg) {
    int e = blockIdx.x * blockDim.x + threadIdx.x;
    if (e < E) atomicAdd(&deg[dst[e]], 1);
}

__global__ void dis_kernel(const int* __restrict__ deg, float* __restrict__ dis, int n) {
    int i = blockIdx.x * blockDim.x + threadIdx.x;
    if (i < n) dis[i] = rsqrtf((float)deg[i] + 1.0f);
}

// ---------------------------------------------------------------------------
// register-tiled SGEMM:  H[n,M] = (relu?)X[n,K] @ W[K,M]
// block: 64 rows x M cols, 256 threads, BK=32 staging
// ---------------------------------------------------------------------------
template <int K, int M, bool RELU>
__global__ __launch_bounds__(256)
void gemm_kernel(const float* __restrict__ X, const float* __restrict__ W,
                 float* __restrict__ H, int n)
{
    constexpr int BM = 64, BK = 32;
    constexpr int CM = M / 16;               // cols per thread (4 or 2)
    __shared__ float xs[BK][BM + 1];         // transposed X tile
    __shared__ float ws[BK][M];

    const int tid = threadIdx.x;
    const int tx = tid & 15, ty = tid >> 4;
    const int row0 = blockIdx.x * BM;

    float acc[4][CM];
#pragma unroll
    for (int r = 0; r < 4; r++)
#pragma unroll
        for (int c = 0; c < CM; c++) acc[r][c] = 0.f;

    for (int k0 = 0; k0 < K; k0 += BK) {
        // X tile: 64 rows x 32 k, loaded coalesced, stored transposed
#pragma unroll
        for (int round = 0; round < 2; round++) {
            int r = (tid >> 3) + round * 32;
            int koff = (tid & 7) * 4;
            int row = row0 + r;
            float4 v = make_float4(0.f, 0.f, 0.f, 0.f);
            if (row < n) v = *(const float4*)(X + (size_t)row * K + k0 + koff);
            if (RELU) {
                v.x = fmaxf(v.x, 0.f); v.y = fmaxf(v.y, 0.f);
                v.z = fmaxf(v.z, 0.f); v.w = fmaxf(v.w, 0.f);
            }
            xs[koff + 0][r] = v.x; xs[koff + 1][r] = v.y;
            xs[koff + 2][r] = v.z; xs[koff + 3][r] = v.w;
        }
        // W tile
#pragma unroll
        for (int idx = tid * 4; idx < BK * M; idx += 256 * 4) {
            int kk = idx / M, m = idx % M;
            *(float4*)&ws[kk][m] = *(const float4*)(W + (size_t)(k0 + kk) * M + m);
        }
        __syncthreads();

#pragma unroll
        for (int kk = 0; kk < BK; kk++) {
            float a[4], b[CM];
#pragma unroll
            for (int r = 0; r < 4; r++) a[r] = xs[kk][ty * 4 + r];
#pragma unroll
            for (int c = 0; c < CM; c++) b[c] = ws[kk][tx * CM + c];
#pragma unroll
            for (int r = 0; r < 4; r++)
#pragma unroll
                for (int c = 0; c < CM; c++)
                    acc[r][c] = fmaf(a[r], b[c], acc[r][c]);
        }
        __syncthreads();
    }

#pragma unroll
    for (int r = 0; r < 4; r++) {
        int row = row0 + ty * 4 + r;
        if (row < n) {
#pragma unroll
            for (int c = 0; c < CM; c++)
                H[(size_t)row * M + tx * CM + c] = acc[r][c];
        }
    }
}

// ---------------------------------------------------------------------------
// self-loop + bias init:  y[i,:] = h[i,:] * dis[i]^2 + b[:]
// vectorized x4 (D % 4 == 0)
// ---------------------------------------------------------------------------
template <int D>
__global__ void selfinit_kernel(const float* __restrict__ h, const float* __restrict__ dis,
                                const float* __restrict__ bias, float* __restrict__ y, int n)
{
    int t = blockIdx.x * blockDim.x + threadIdx.x;
    int total = n * (D / 4);
    if (t >= total) return;
    int elem0 = t * 4;
    int node = elem0 / D;
    int j = elem0 % D;
    float s = dis[node]; s = s * s;
    float4 v = *(const float4*)(h + (size_t)elem0);
    float4 b = *(const float4*)(bias + j);
    float4 o;
    o.x = fmaf(v.x, s, b.x);
    o.y = fmaf(v.y, s, b.y);
    o.z = fmaf(v.z, s, b.z);
    o.w = fmaf(v.w, s, b.w);
    *(float4*)(y + (size_t)elem0) = o;
}

// ---------------------------------------------------------------------------
// edge scatter:  y[dst,:] += h[src,:] * dis[src]*dis[dst]
// D/4 threads per edge, one float4 + one red.global.add.v4.f32 per thread
// ---------------------------------------------------------------------------
template <int D>
__global__ void scatter_kernel(const float* __restrict__ h,
                               const int* __restrict__ src_arr,
                               const int* __restrict__ dst_arr,
                               const float* __restrict__ dis,
                               float* __restrict__ y, int E)
{
    constexpr int TPE = D / 4;               // threads per edge (16 or 8)
    int gid = blockIdx.x * blockDim.x + threadIdx.x;
    int e = gid / TPE;
    int lane = gid % TPE;
    if (e >= E) return;
    int s = src_arr[e];
    int d = dst_arr[e];
    float norm = dis[s] * dis[d];
    float4 v = *(const float4*)(h + (size_t)s * D + lane * 4);
    v.x *= norm; v.y *= norm; v.z *= norm; v.w *= norm;
    float* p = y + (size_t)d * D + lane * 4;
    asm volatile("red.global.add.v4.f32 [%0], {%1,%2,%3,%4};"
                 :: "l"(p), "f"(v.x), "f"(v.y), "f"(v.z), "f"(v.w)
                 : "memory");
}

// ---------------------------------------------------------------------------
// host launcher
// ---------------------------------------------------------------------------
extern "C" void kernel_launch(void* const* d_in, const int* in_sizes, int n_in,
                              void* d_out, int out_size)
{
    const float* feat = (const float*)d_in[0];
    const int*   ei   = (const int*)d_in[1];
    const float* W0   = (const float*)d_in[2];
    const float* b0   = (const float*)d_in[3];
    const float* W1   = (const float*)d_in[4];
    const float* b1   = (const float*)d_in[5];
    const float* W2   = (const float*)d_in[6];
    const float* b2   = (const float*)d_in[7];
    float* out = (float*)d_out;

    const int n = in_sizes[0] / 128;
    const int E = in_sizes[1] / 2;
    const int* src = ei;
    const int* dst = ei + E;

    float* h;  cudaGetSymbolAddress((void**)&h,  g_h);
    float* y;  cudaGetSymbolAddress((void**)&y,  g_y);
    int*   deg; cudaGetSymbolAddress((void**)&deg, g_deg);
    float* dis; cudaGetSymbolAddress((void**)&dis, g_dis);

    const int T = 256;
    auto cdiv = [](int a, int b) { return (a + b - 1) / b; };

    // normalization
    zero_deg_kernel<<<cdiv(n, T), T>>>(deg, n);
    degree_kernel<<<cdiv(E, T), T>>>(dst, E, deg);
    dis_kernel<<<cdiv(n, T), T>>>(deg, dis, n);

    // layer 0: 128 -> 64
    gemm_kernel<128, 64, false><<<cdiv(n, 64), 256>>>(feat, W0, h, n);
    selfinit_kernel<64><<<cdiv(n * 16, T), T>>>(h, dis, b0, y, n);
    scatter_kernel<64><<<cdiv(E * 16, T), T>>>(h, src, dst, dis, y, E);

    // layer 1: 64 -> 64 (relu on input)
    gemm_kernel<64, 64, true><<<cdiv(n, 64), 256>>>(y, W1, h, n);
    selfinit_kernel<64><<<cdiv(n * 16, T), T>>>(h, dis, b1, y, n);
    scatter_kernel<64><<<cdiv(E * 16, T), T>>>(h, src, dst, dis, y, E);

    // layer 2: 64 -> 32 (relu on input), writes d_out directly
    gemm_kernel<64, 32, true><<<cdiv(n, 64), 256>>>(y, W2, h, n);
    selfinit_kernel<32><<<cdiv(n * 8, T), T>>>(h, dis, b2, out, n);
    scatter_kernel<32><<<cdiv(E * 8, T), T>>>(h, src, dst, dis, out, E);
}

// round 2
// speedup vs baseline: 2.5984x; 2.5984x over previous
#include <cuda_runtime.h>
#include <cuda_bf16.h>
#include <cstdint>

#define MAX_N 100000
#define MAX_E 1600000

// Scratch (device globals: no allocation allowed)
__device__ float g_h[(size_t)MAX_N * 64];    // dis-scaled post-GEMM features
__device__ float g_y[(size_t)MAX_N * 64];    // aggregated features
__device__ int   g_deg[MAX_N];               // in-degree (excl self loop)
__device__ float g_dis[MAX_N];               // rsqrt(deg+1)
__device__ int   g_offs[MAX_N];              // CSR row offsets (exclusive prefix of deg)
__device__ int   g_cursor[MAX_N];            // fill cursors
__device__ int   g_nbr[MAX_E];               // src ids sorted by dst
__device__ int   g_bsum[256];                // block sums for scan

// ---------------------------------------------------------------------------
// degree / normalization
// ---------------------------------------------------------------------------
__global__ void zero_deg_kernel(int* __restrict__ deg, int n) {
    int i = blockIdx.x * blockDim.x + threadIdx.x;
    if (i < n) deg[i] = 0;
}

__global__ void degree_kernel(const int* __restrict__ dst, int E, int* __restrict__ deg) {
    int e = blockIdx.x * blockDim.x + threadIdx.x;
    if (e < E) atomicAdd(&deg[dst[e]], 1);
}

__global__ void dis_kernel(const int* __restrict__ deg, float* __restrict__ dis, int n) {
    int i = blockIdx.x * blockDim.x + threadIdx.x;
    if (i < n) dis[i] = rsqrtf((float)deg[i] + 1.0f);
}

// ---------------------------------------------------------------------------
// prefix scan of deg -> offs   (1024 elems / block)
// ---------------------------------------------------------------------------
__global__ __launch_bounds__(256)
void scan1_kernel(const int* __restrict__ deg, int n,
                  int* __restrict__ offs, int* __restrict__ bsum)
{
    __shared__ int warp_sums[8];
    const int base = blockIdx.x * 1024;
    const int tid = threadIdx.x;
    int v[4];
    int s = 0;
#pragma unroll
    for (int i = 0; i < 4; i++) {
        int idx = base + tid * 4 + i;
        v[i] = (idx < n) ? deg[idx] : 0;
        s += v[i];
    }
    const int lane = tid & 31, wid = tid >> 5;
    int ps = s;
#pragma unroll
    for (int d = 1; d < 32; d <<= 1) {
        int t = __shfl_up_sync(~0u, ps, d);
        if (lane >= d) ps += t;
    }
    if (lane == 31) warp_sums[wid] = ps;
    __syncthreads();
    if (tid < 8) {
        int w = warp_sums[tid];
#pragma unroll
        for (int d = 1; d < 8; d <<= 1) {
            int t = __shfl_up_sync(0xffu, w, d);
            if (tid >= d) w += t;
        }
        warp_sums[tid] = w;
    }
    __syncthreads();
    int thread_excl = (wid > 0 ? warp_sums[wid - 1] : 0) + (ps - s);
    int run = thread_excl;
#pragma unroll
    for (int i = 0; i < 4; i++) {
        int idx = base + tid * 4 + i;
        if (idx < n) offs[idx] = run;
        run += v[i];
    }
    if (tid == 255) bsum[blockIdx.x] = thread_excl + s;   // block total
}

__global__ void scan2_kernel(int* __restrict__ bsum, int nb)
{
    // single block, 128 threads, nb <= 128
    const int tid = threadIdx.x;
    const int lane = tid & 31, wid = tid >> 5;
    __shared__ int wsum[4];
    int v = (tid < nb) ? bsum[tid] : 0;
    int ps = v;
#pragma unroll
    for (int d = 1; d < 32; d <<= 1) {
        int t = __shfl_up_sync(~0u, ps, d);
        if (lane >= d) ps += t;
    }
    if (lane == 31) wsum[wid] = ps;
    __syncthreads();
    if (tid < 4) {
        int w = wsum[tid];
#pragma unroll
        for (int d = 1; d < 4; d <<= 1) {
            int t = __shfl_up_sync(0xfu, w, d);
            if (tid >= d) w += t;
        }
        wsum[tid] = w;
    }
    __syncthreads();
    int incl = ps + (wid > 0 ? wsum[wid - 1] : 0);
    if (tid < nb) bsum[tid] = incl - v;                   // exclusive
}

__global__ void scan3_kernel(int* __restrict__ offs, int* __restrict__ cursor,
                             const int* __restrict__ bsum, int n)
{
    int i = blockIdx.x * blockDim.x + threadIdx.x;
    if (i < n) {
        int o = offs[i] + bsum[i >> 10];
        offs[i] = o;
        cursor[i] = o;
    }
}

__global__ void fill_kernel(const int* __restrict__ src, const int* __restrict__ dst,
                            int E, int* __restrict__ cursor, int* __restrict__ nbr)
{
    int e = blockIdx.x * blockDim.x + threadIdx.x;
    if (e < E) {
        int d = dst[e];
        int p = atomicAdd(&cursor[d], 1);
        nbr[p] = src[e];
    }
}

// ---------------------------------------------------------------------------
// register-tiled SGEMM with fused relu-on-load and dis-scale epilogue:
//   H[row,:] = ((relu?)X[row,:] @ W) * dis[row]
// block: 128 rows x M cols, 256 threads, thread tile 8x(M/16), BK=32 staging
// ---------------------------------------------------------------------------
template <int K, int M, bool RELU>
__global__ __launch_bounds__(256)
void gemm_kernel(const float* __restrict__ X, const float* __restrict__ W,
                 const float* __restrict__ dis, float* __restrict__ H, int n)
{
    constexpr int BM = 128, BK = 32;
    constexpr int CM = M / 16;                 // 4 (M=64) or 2 (M=32)
    __shared__ float xs[BM][BK + 4];           // stride 36 floats: float4-alignable
    __shared__ float ws[BK][M];

    const int tid = threadIdx.x;
    const int tx = tid & 15, ty = tid >> 4;
    const int row0 = blockIdx.x * BM;

    float acc[8][CM];
#pragma unroll
    for (int r = 0; r < 8; r++)
#pragma unroll
        for (int c = 0; c < CM; c++) acc[r][c] = 0.f;

    for (int k0 = 0; k0 < K; k0 += BK) {
        // X tile: 128 rows x 32 k
#pragma unroll
        for (int round = 0; round < 4; round++) {
            int r = (tid >> 3) + round * 32;
            int koff = (tid & 7) * 4;
            int row = row0 + r;
            float4 v = make_float4(0.f, 0.f, 0.f, 0.f);
            if (row < n) v = *(const float4*)(X + (size_t)row * K + k0 + koff);
            if (RELU) {
                v.x = fmaxf(v.x, 0.f); v.y = fmaxf(v.y, 0.f);
                v.z = fmaxf(v.z, 0.f); v.w = fmaxf(v.w, 0.f);
            }
            *(float4*)&xs[r][koff] = v;
        }
        // W tile
#pragma unroll
        for (int idx = tid * 4; idx < BK * M; idx += 1024) {
            int kk = idx / M, m = idx % M;
            *(float4*)&ws[kk][m] = *(const float4*)(W + (size_t)(k0 + kk) * M + m);
        }
        __syncthreads();

#pragma unroll
        for (int kk = 0; kk < BK; kk++) {
            float b[CM];
            if (CM == 4) {
                float4 bb = *(const float4*)&ws[kk][tx * 4];
                b[0] = bb.x; b[1] = bb.y; b[2] = bb.z; b[3] = bb.w;
            } else {
                float2 bb = *(const float2*)&ws[kk][tx * 2];
                b[0] = bb.x; b[1] = bb.y;
            }
#pragma unroll
            for (int r = 0; r < 8; r++) {
                float a = xs[ty + 16 * r][kk];   // rows interleaved: conflict-free
#pragma unroll
                for (int c = 0; c < CM; c++)
                    acc[r][c] = fmaf(a, b[c], acc[r][c]);
            }
        }
        __syncthreads();
    }

    // epilogue: scale by dis[row], vectorized store
#pragma unroll
    for (int r = 0; r < 8; r++) {
        int row = row0 + ty + 16 * r;
        if (row < n) {
            float s = dis[row];
            if (CM == 4) {
                float4 o = make_float4(acc[r][0] * s, acc[r][1] * s,
                                       acc[r][2] * s, acc[r][3] * s);
                *(float4*)(H + (size_t)row * M + tx * 4) = o;
            } else {
                float2 o = make_float2(acc[r][0] * s, acc[r][1] * s);
                *(float2*)(H + (size_t)row * M + tx * 2) = o;
            }
        }
    }
}

// ---------------------------------------------------------------------------
// pull-style CSR aggregation:
//   y[d,:] = dis[d] * ( h[d,:] + sum_{s in N(d)} h[s,:] ) + b[:]
// (h already carries dis[src] from the GEMM epilogue)
// D/4 threads per node, float4 lanes, 4-deep neighbor unroll for MLP
// ---------------------------------------------------------------------------
template <int D>
__global__ __launch_bounds__(256)
void aggregate_kernel(const float* __restrict__ h,
                      const int* __restrict__ offs,
                      const int* __restrict__ deg,
                      const int* __restrict__ nbr,
                      const float* __restrict__ dis,
                      const float* __restrict__ bias,
                      float* __restrict__ y, int n)
{
    constexpr int TPN = D / 4;
    int gid = blockIdx.x * blockDim.x + threadIdx.x;
    int node = gid / TPN;
    int lane = gid % TPN;
    if (node >= n) return;
    const int col = lane * 4;
    const int start = offs[node];
    const int cnt = deg[node];

    float4 acc = *(const float4*)(h + (size_t)node * D + col);   // self loop

    int j = 0;
    for (; j + 4 <= cnt; j += 4) {
        int s0 = nbr[start + j + 0];
        int s1 = nbr[start + j + 1];
        int s2 = nbr[start + j + 2];
        int s3 = nbr[start + j + 3];
        float4 v0 = *(const float4*)(h + (size_t)s0 * D + col);
        float4 v1 = *(const float4*)(h + (size_t)s1 * D + col);
        float4 v2 = *(const float4*)(h + (size_t)s2 * D + col);
        float4 v3 = *(const float4*)(h + (size_t)s3 * D + col);
        acc.x += (v0.x + v1.x) + (v2.x + v3.x);
        acc.y += (v0.y + v1.y) + (v2.y + v3.y);
        acc.z += (v0.z + v1.z) + (v2.z + v3.z);
        acc.w += (v0.w + v1.w) + (v2.w + v3.w);
    }
    for (; j < cnt; j++) {
        int s = nbr[start + j];
        float4 v = *(const float4*)(h + (size_t)s * D + col);
        acc.x += v.x; acc.y += v.y; acc.z += v.z; acc.w += v.w;
    }

    float dd = dis[node];
    float4 b = *(const float4*)(bias + col);
    float4 o;
    o.x = fmaf(acc.x, dd, b.x);
    o.y = fmaf(acc.y, dd, b.y);
    o.z = fmaf(acc.z, dd, b.z);
    o.w = fmaf(acc.w, dd, b.w);
    *(float4*)(y + (size_t)node * D + col) = o;
}

// ---------------------------------------------------------------------------
// host launcher
// ---------------------------------------------------------------------------
extern "C" void kernel_launch(void* const* d_in, const int* in_sizes, int n_in,
                              void* d_out, int out_size)
{
    const float* feat = (const float*)d_in[0];
    const int*   ei   = (const int*)d_in[1];
    const float* W0   = (const float*)d_in[2];
    const float* b0   = (const float*)d_in[3];
    const float* W1   = (const float*)d_in[4];
    const float* b1   = (const float*)d_in[5];
    const float* W2   = (const float*)d_in[6];
    const float* b2   = (const float*)d_in[7];
    float* out = (float*)d_out;

    const int n = in_sizes[0] / 128;
    const int E = in_sizes[1] / 2;
    const int* src = ei;
    const int* dst = ei + E;

    float* h;   cudaGetSymbolAddress((void**)&h,   g_h);
    float* y;   cudaGetSymbolAddress((void**)&y,   g_y);
    int*   deg; cudaGetSymbolAddress((void**)&deg, g_deg);
    float* dis; cudaGetSymbolAddress((void**)&dis, g_dis);
    int*   offs;   cudaGetSymbolAddress((void**)&offs,   g_offs);
    int*   cursor; cudaGetSymbolAddress((void**)&cursor, g_cursor);
    int*   nbr;    cudaGetSymbolAddress((void**)&nbr,    g_nbr);
    int*   bsum;   cudaGetSymbolAddress((void**)&bsum,   g_bsum);

    const int T = 256;
    auto cdiv = [](int a, int b) { return (a + b - 1) / b; };
    const int nb = cdiv(n, 1024);   // scan blocks (<= 128 for n <= 131072)

    // --- normalization + CSR build (shared by all 3 layers) ---
    zero_deg_kernel<<<cdiv(n, T), T>>>(deg, n);
    degree_kernel<<<cdiv(E, T), T>>>(dst, E, deg);
    dis_kernel<<<cdiv(n, T), T>>>(deg, dis, n);
    scan1_kernel<<<nb, 256>>>(deg, n, offs, bsum);
    scan2_kernel<<<1, 128>>>(bsum, nb);
    scan3_kernel<<<cdiv(n, T), T>>>(offs, cursor, bsum, n);
    fill_kernel<<<cdiv(E, T), T>>>(src, dst, E, cursor, nbr);

    // --- layer 0: 128 -> 64 ---
    gemm_kernel<128, 64, false><<<cdiv(n, 128), 256>>>(feat, W0, dis, h, n);
    aggregate_kernel<64><<<cdiv(n * 16, T), T>>>(h, offs, deg, nbr, dis, b0, y, n);

    // --- layer 1: 64 -> 64 (relu on load) ---
    gemm_kernel<64, 64, true><<<cdiv(n, 128), 256>>>(y, W1, dis, h, n);
    aggregate_kernel<64><<<cdiv(n * 16, T), T>>>(h, offs, deg, nbr, dis, b1, y, n);

    // --- layer 2: 64 -> 32 (relu on load), direct to d_out ---
    gemm_kernel<64, 32, true><<<cdiv(n, 128), 256>>>(y, W2, dis, h, n);
    aggregate_kernel<32><<<cdiv(n * 8, T), T>>>(h, offs, deg, nbr, dis, b2, out, n);
}

// round 3
// speedup vs baseline: 2.7939x; 1.0752x over previous
#include <cuda_runtime.h>
#include <cuda_fp16.h>
#include <cstdint>

#define MAX_N 100000
#define MAX_E 1600000

// Scratch (device globals: no allocation allowed)
__device__ __half g_h[(size_t)MAX_N * 64];   // dis-scaled post-GEMM features (fp16)
__device__ float  g_y[(size_t)MAX_N * 64];   // aggregated features (fp32)
__device__ int    g_deg[MAX_N];              // in-degree (excl self loop)
__device__ float  g_dis[MAX_N];              // rsqrt(deg+1)
__device__ int    g_offs[MAX_N];             // CSR row offsets
__device__ int    g_cursor[MAX_N];           // fill cursors
__device__ int    g_nbr[MAX_E];              // src ids sorted by dst
__device__ int    g_bsum[256];               // block sums for scan

// ---------------------------------------------------------------------------
// degree / normalization
// ---------------------------------------------------------------------------
__global__ void zero_deg_kernel(int* __restrict__ deg, int n) {
    int i = blockIdx.x * blockDim.x + threadIdx.x;
    if (i < n) deg[i] = 0;
}

__global__ void degree_kernel(const int* __restrict__ dst, int E, int* __restrict__ deg) {
    int e = blockIdx.x * blockDim.x + threadIdx.x;
    if (e < E) atomicAdd(&deg[dst[e]], 1);
}

__global__ void dis_kernel(const int* __restrict__ deg, float* __restrict__ dis, int n) {
    int i = blockIdx.x * blockDim.x + threadIdx.x;
    if (i < n) dis[i] = rsqrtf((float)deg[i] + 1.0f);
}

// ---------------------------------------------------------------------------
// prefix scan of deg -> offs   (1024 elems / block)
// ---------------------------------------------------------------------------
__global__ __launch_bounds__(256)
void scan1_kernel(const int* __restrict__ deg, int n,
                  int* __restrict__ offs, int* __restrict__ bsum)
{
    __shared__ int warp_sums[8];
    const int base = blockIdx.x * 1024;
    const int tid = threadIdx.x;
    int v[4];
    int s = 0;
#pragma unroll
    for (int i = 0; i < 4; i++) {
        int idx = base + tid * 4 + i;
        v[i] = (idx < n) ? deg[idx] : 0;
        s += v[i];
    }
    const int lane = tid & 31, wid = tid >> 5;
    int ps = s;
#pragma unroll
    for (int d = 1; d < 32; d <<= 1) {
        int t = __shfl_up_sync(~0u, ps, d);
        if (lane >= d) ps += t;
    }
    if (lane == 31) warp_sums[wid] = ps;
    __syncthreads();
    if (tid < 8) {
        int w = warp_sums[tid];
#pragma unroll
        for (int d = 1; d < 8; d <<= 1) {
            int t = __shfl_up_sync(0xffu, w, d);
            if (tid >= d) w += t;
        }
        warp_sums[tid] = w;
    }
    __syncthreads();
    int thread_excl = (wid > 0 ? warp_sums[wid - 1] : 0) + (ps - s);
    int run = thread_excl;
#pragma unroll
    for (int i = 0; i < 4; i++) {
        int idx = base + tid * 4 + i;
        if (idx < n) offs[idx] = run;
        run += v[i];
    }
    if (tid == 255) bsum[blockIdx.x] = thread_excl + s;
}

__global__ void scan2_kernel(int* __restrict__ bsum, int nb)
{
    const int tid = threadIdx.x;
    const int lane = tid & 31, wid = tid >> 5;
    __shared__ int wsum[4];
    int v = (tid < nb) ? bsum[tid] : 0;
    int ps = v;
#pragma unroll
    for (int d = 1; d < 32; d <<= 1) {
        int t = __shfl_up_sync(~0u, ps, d);
        if (lane >= d) ps += t;
    }
    if (lane == 31) wsum[wid] = ps;
    __syncthreads();
    if (tid < 4) {
        int w = wsum[tid];
#pragma unroll
        for (int d = 1; d < 4; d <<= 1) {
            int t = __shfl_up_sync(0xfu, w, d);
            if (tid >= d) w += t;
        }
        wsum[tid] = w;
    }
    __syncthreads();
    int incl = ps + (wid > 0 ? wsum[wid - 1] : 0);
    if (tid < nb) bsum[tid] = incl - v;
}

__global__ void scan3_kernel(int* __restrict__ offs, int* __restrict__ cursor,
                             const int* __restrict__ bsum, int n)
{
    int i = blockIdx.x * blockDim.x + threadIdx.x;
    if (i < n) {
        int o = offs[i] + bsum[i >> 10];
        offs[i] = o;
        cursor[i] = o;
    }
}

__global__ void fill_kernel(const int* __restrict__ src, const int* __restrict__ dst,
                            int E, int* __restrict__ cursor, int* __restrict__ nbr)
{
    int e = blockIdx.x * blockDim.x + threadIdx.x;
    if (e < E) {
        int d = dst[e];
        int p = atomicAdd(&cursor[d], 1);
        nbr[p] = src[e];
    }
}

// ---------------------------------------------------------------------------
// register-tiled SGEMM, relu-on-load, dis-scale + fp16-convert epilogue:
//   H[row,:] = fp16( ((relu?)X[row,:] @ W) * dis[row] )
// ---------------------------------------------------------------------------
template <int K, int M, bool RELU>
__global__ __launch_bounds__(256)
void gemm_kernel(const float* __restrict__ X, const float* __restrict__ W,
                 const float* __restrict__ dis, __half* __restrict__ H, int n)
{
    constexpr int BM = 128, BK = 32;
    constexpr int CM = M / 16;                 // 4 (M=64) or 2 (M=32)
    __shared__ float xs[BM][BK + 4];
    __shared__ float ws[BK][M];

    const int tid = threadIdx.x;
    const int tx = tid & 15, ty = tid >> 4;
    const int row0 = blockIdx.x * BM;

    float acc[8][CM];
#pragma unroll
    for (int r = 0; r < 8; r++)
#pragma unroll
        for (int c = 0; c < CM; c++) acc[r][c] = 0.f;

    for (int k0 = 0; k0 < K; k0 += BK) {
#pragma unroll
        for (int round = 0; round < 4; round++) {
            int r = (tid >> 3) + round * 32;
            int koff = (tid & 7) * 4;
            int row = row0 + r;
            float4 v = make_float4(0.f, 0.f, 0.f, 0.f);
            if (row < n) v = *(const float4*)(X + (size_t)row * K + k0 + koff);
            if (RELU) {
                v.x = fmaxf(v.x, 0.f); v.y = fmaxf(v.y, 0.f);
                v.z = fmaxf(v.z, 0.f); v.w = fmaxf(v.w, 0.f);
            }
            *(float4*)&xs[r][koff] = v;
        }
#pragma unroll
        for (int idx = tid * 4; idx < BK * M; idx += 1024) {
            int kk = idx / M, m = idx % M;
            *(float4*)&ws[kk][m] = *(const float4*)(W + (size_t)(k0 + kk) * M + m);
        }
        __syncthreads();

#pragma unroll
        for (int kk = 0; kk < BK; kk++) {
            float b[CM];
            if (CM == 4) {
                float4 bb = *(const float4*)&ws[kk][tx * 4];
                b[0] = bb.x; b[1] = bb.y; b[2] = bb.z; b[3] = bb.w;
            } else {
                float2 bb = *(const float2*)&ws[kk][tx * 2];
                b[0] = bb.x; b[1] = bb.y;
            }
#pragma unroll
            for (int r = 0; r < 8; r++) {
                float a = xs[ty + 16 * r][kk];
#pragma unroll
                for (int c = 0; c < CM; c++)
                    acc[r][c] = fmaf(a, b[c], acc[r][c]);
            }
        }
        __syncthreads();
    }

#pragma unroll
    for (int r = 0; r < 8; r++) {
        int row = row0 + ty + 16 * r;
        if (row < n) {
            float s = dis[row];
            if (CM == 4) {
                __half2 p0 = __floats2half2_rn(acc[r][0] * s, acc[r][1] * s);
                __half2 p1 = __floats2half2_rn(acc[r][2] * s, acc[r][3] * s);
                uint2 o = make_uint2(*(uint32_t*)&p0, *(uint32_t*)&p1);
                *(uint2*)(H + (size_t)row * M + tx * 4) = o;
            } else {
                __half2 p0 = __floats2half2_rn(acc[r][0] * s, acc[r][1] * s);
                *(uint32_t*)(H + (size_t)row * M + tx * 2) = *(uint32_t*)&p0;
            }
        }
    }
}

// ---------------------------------------------------------------------------
// pull-style CSR aggregation (fp16 gather, fp32 accumulate):
//   y[d,:] = dis[d] * ( h[d,:] + sum_{s in N(d)} h[s,:] ) + b[:]
// D/8 threads per node; each thread owns 8 halves (one 16B uint4 lane)
// ---------------------------------------------------------------------------
__device__ __forceinline__ void acc_row8(float* acc, const __half* p) {
    uint4 raw = *(const uint4*)p;
    const __half2* h2 = (const __half2*)&raw;
#pragma unroll
    for (int q = 0; q < 4; q++) {
        float2 f = __half22float2(h2[q]);
        acc[q * 2 + 0] += f.x;
        acc[q * 2 + 1] += f.y;
    }
}

template <int D>
__global__ __launch_bounds__(256)
void aggregate_kernel(const __half* __restrict__ h,
                      const int* __restrict__ offs,
                      const int* __restrict__ deg,
                      const int* __restrict__ nbr,
                      const float* __restrict__ dis,
                      const float* __restrict__ bias,
                      float* __restrict__ y, int n)
{
    constexpr int TPN = D / 8;                // 8 (D=64) or 4 (D=32)
    int gid = blockIdx.x * blockDim.x + threadIdx.x;
    int node = gid / TPN;
    int lane = gid % TPN;
    if (node >= n) return;
    const int col = lane * 8;
    const int start = offs[node];
    const int cnt = deg[node];

    float acc[8];
    {   // self loop seed
        uint4 raw = *(const uint4*)(h + (size_t)node * D + col);
        const __half2* h2 = (const __half2*)&raw;
#pragma unroll
        for (int q = 0; q < 4; q++) {
            float2 f = __half22float2(h2[q]);
            acc[q * 2 + 0] = f.x;
            acc[q * 2 + 1] = f.y;
        }
    }

    int j = 0;
    for (; j + 4 <= cnt; j += 4) {
        int s0 = nbr[start + j + 0];
        int s1 = nbr[start + j + 1];
        int s2 = nbr[start + j + 2];
        int s3 = nbr[start + j + 3];
        acc_row8(acc, h + (size_t)s0 * D + col);
        acc_row8(acc, h + (size_t)s1 * D + col);
        acc_row8(acc, h + (size_t)s2 * D + col);
        acc_row8(acc, h + (size_t)s3 * D + col);
    }
    for (; j < cnt; j++) {
        int s = nbr[start + j];
        acc_row8(acc, h + (size_t)s * D + col);
    }

    float dd = dis[node];
    float4 b0 = *(const float4*)(bias + col);
    float4 b1 = *(const float4*)(bias + col + 4);
    float4 o0, o1;
    o0.x = fmaf(acc[0], dd, b0.x); o0.y = fmaf(acc[1], dd, b0.y);
    o0.z = fmaf(acc[2], dd, b0.z); o0.w = fmaf(acc[3], dd, b0.w);
    o1.x = fmaf(acc[4], dd, b1.x); o1.y = fmaf(acc[5], dd, b1.y);
    o1.z = fmaf(acc[6], dd, b1.z); o1.w = fmaf(acc[7], dd, b1.w);
    *(float4*)(y + (size_t)node * D + col) = o0;
    *(float4*)(y + (size_t)node * D + col + 4) = o1;
}

// ---------------------------------------------------------------------------
// host launcher
// ---------------------------------------------------------------------------
extern "C" void kernel_launch(void* const* d_in, const int* in_sizes, int n_in,
                              void* d_out, int out_size)
{
    const float* feat = (const float*)d_in[0];
    const int*   ei   = (const int*)d_in[1];
    const float* W0   = (const float*)d_in[2];
    const float* b0   = (const float*)d_in[3];
    const float* W1   = (const float*)d_in[4];
    const float* b1   = (const float*)d_in[5];
    const float* W2   = (const float*)d_in[6];
    const float* b2   = (const float*)d_in[7];
    float* out = (float*)d_out;

    const int n = in_sizes[0] / 128;
    const int E = in_sizes[1] / 2;
    const int* src = ei;
    const int* dst = ei + E;

    __half* h;  cudaGetSymbolAddress((void**)&h,   g_h);
    float*  y;  cudaGetSymbolAddress((void**)&y,   g_y);
    int*    deg; cudaGetSymbolAddress((void**)&deg, g_deg);
    float*  dis; cudaGetSymbolAddress((void**)&dis, g_dis);
    int*    offs;   cudaGetSymbolAddress((void**)&offs,   g_offs);
    int*    cursor; cudaGetSymbolAddress((void**)&cursor, g_cursor);
    int*    nbr;    cudaGetSymbolAddress((void**)&nbr,    g_nbr);
    int*    bsum;   cudaGetSymbolAddress((void**)&bsum,   g_bsum);

    const int T = 256;
    auto cdiv = [](int a, int b) { return (a + b - 1) / b; };
    const int nb = cdiv(n, 1024);

    // --- normalization + CSR build (shared by all 3 layers) ---
    zero_deg_kernel<<<cdiv(n, T), T>>>(deg, n);
    degree_kernel<<<cdiv(E, T), T>>>(dst, E, deg);
    dis_kernel<<<cdiv(n, T), T>>>(deg, dis, n);
    scan1_kernel<<<nb, 256>>>(deg, n, offs, bsum);
    scan2_kernel<<<1, 128>>>(bsum, nb);
    scan3_kernel<<<cdiv(n, T), T>>>(offs, cursor, bsum, n);
    fill_kernel<<<cdiv(E, T), T>>>(src, dst, E, cursor, nbr);

    // --- layer 0: 128 -> 64 ---
    gemm_kernel<128, 64, false><<<cdiv(n, 128), 256>>>(feat, W0, dis, h, n);
    aggregate_kernel<64><<<cdiv(n * 8, T), T>>>(h, offs, deg, nbr, dis, b0, y, n);

    // --- layer 1: 64 -> 64 (relu on load) ---
    gemm_kernel<64, 64, true><<<cdiv(n, 128), 256>>>(y, W1, dis, h, n);
    aggregate_kernel<64><<<cdiv(n * 8, T), T>>>(h, offs, deg, nbr, dis, b1, y, n);

    // --- layer 2: 64 -> 32 (relu on load), direct to d_out ---
    gemm_kernel<64, 32, true><<<cdiv(n, 128), 256>>>(y, W2, dis, h, n);
    aggregate_kernel<32><<<cdiv(n * 4, T), T>>>(h, offs, deg, nbr, dis, b2, out, n);
}